// round 12
// baseline (speedup 1.0000x reference)
#include <cuda_runtime.h>
#include <cuda_fp16.h>
#include <cuda_bf16.h>
#include <math_constants.h>
#include <cstdint>
#include <cstring>

// Problem constants (fixed by reference setup_inputs)
#define BATCH   2
#define SEQ     4096
#define DMODEL  768
#define NHEADS  12
#define DHEAD   64
#define BT      (BATCH * SEQ)        // 8192
#define C3      (3 * DMODEL)         // 2304

// Scratch (device globals: allocation-free per harness rules)
__device__ float         g_q[(size_t)BT * DMODEL];    // Q fp32
__device__ __nv_bfloat16 g_xh[(size_t)BT * DMODEL];   // x hi
__device__ __nv_bfloat16 g_xl[(size_t)BT * DMODEL];   // x lo
__device__ __nv_bfloat16 g_wqh[(size_t)DMODEL * C3];  // W_qkv hi
__device__ __nv_bfloat16 g_wql[(size_t)DMODEL * C3];  // W_qkv lo
__device__ __nv_bfloat16 g_wph[(size_t)DMODEL * DMODEL]; // W_proj hi
__device__ __nv_bfloat16 g_wpl[(size_t)DMODEL * DMODEL]; // W_proj lo
__device__ __nv_bfloat16 g_ath[(size_t)BT * DMODEL];  // att out hi
__device__ __nv_bfloat16 g_atl[(size_t)BT * DMODEL];  // att out lo
__device__ __nv_bfloat16 g_kh[(size_t)BT * DMODEL];   // K bf16 hi
__device__ __nv_bfloat16 g_kl[(size_t)BT * DMODEL];   // K bf16 lo
__device__ __half        g_vh[(size_t)BT * DMODEL];   // V fp16

// ---------------------------------------------------------------------------
// PTX helpers
// ---------------------------------------------------------------------------
__device__ __forceinline__ float fast_exp2(float x) {
    float y;
    asm("ex2.approx.f32 %0, %1;" : "=f"(y) : "f"(x));
    return y;
}

__device__ __forceinline__ uint32_t h2_as_u32(__half2 h) {
    uint32_t r; memcpy(&r, &h, 4); return r;
}
__device__ __forceinline__ uint32_t bf2_as_u32(__nv_bfloat162 h) {
    uint32_t r; memcpy(&r, &h, 4); return r;
}

__device__ __forceinline__ void mma_f16(float c[4], const uint32_t a[4],
                                        uint32_t b0, uint32_t b1) {
    asm volatile(
        "mma.sync.aligned.m16n8k16.row.col.f32.f16.f16.f32 "
        "{%0,%1,%2,%3},{%4,%5,%6,%7},{%8,%9},{%0,%1,%2,%3};"
        : "+f"(c[0]), "+f"(c[1]), "+f"(c[2]), "+f"(c[3])
        : "r"(a[0]), "r"(a[1]), "r"(a[2]), "r"(a[3]), "r"(b0), "r"(b1));
}

__device__ __forceinline__ void mma_bf16(float c[4], const uint32_t a[4],
                                         uint32_t b0, uint32_t b1) {
    asm volatile(
        "mma.sync.aligned.m16n8k16.row.col.f32.bf16.bf16.f32 "
        "{%0,%1,%2,%3},{%4,%5,%6,%7},{%8,%9},{%0,%1,%2,%3};"
        : "+f"(c[0]), "+f"(c[1]), "+f"(c[2]), "+f"(c[3])
        : "r"(a[0]), "r"(a[1]), "r"(a[2]), "r"(a[3]), "r"(b0), "r"(b1));
}

__device__ __forceinline__ void ldmatrix_x4(uint32_t& r0, uint32_t& r1,
                                            uint32_t& r2, uint32_t& r3,
                                            uint32_t addr) {
    asm volatile(
        "ldmatrix.sync.aligned.m8n8.x4.shared.b16 {%0,%1,%2,%3}, [%4];"
        : "=r"(r0), "=r"(r1), "=r"(r2), "=r"(r3)
        : "r"(addr));
}

__device__ __forceinline__ void ldmatrix_x4_trans(uint32_t& r0, uint32_t& r1,
                                                  uint32_t& r2, uint32_t& r3,
                                                  uint32_t addr) {
    asm volatile(
        "ldmatrix.sync.aligned.m8n8.x4.trans.shared.b16 {%0,%1,%2,%3}, [%4];"
        : "=r"(r0), "=r"(r1), "=r"(r2), "=r"(r3)
        : "r"(addr));
}

__device__ __forceinline__ void cp_async16(uint32_t smem, const void* gmem) {
    asm volatile("cp.async.cg.shared.global [%0], [%1], 16;"
                 :: "r"(smem), "l"(gmem));
}
__device__ __forceinline__ void cp_commit() {
    asm volatile("cp.async.commit_group;");
}

// ---------------------------------------------------------------------------
// fp32 -> bf16 hi/lo split (streaming). One thread per float4.
// ---------------------------------------------------------------------------
__global__ __launch_bounds__(256)
void split32_kernel(const float* __restrict__ src,
                    __nv_bfloat16* __restrict__ dh,
                    __nv_bfloat16* __restrict__ dl)
{
    const size_t i4 = (size_t)blockIdx.x * 256 + threadIdx.x;
    float4 v = reinterpret_cast<const float4*>(src)[i4];
    float f[4] = {v.x, v.y, v.z, v.w};
    __nv_bfloat16 hi[4], lo[4];
    #pragma unroll
    for (int j = 0; j < 4; j++) {
        hi[j] = __float2bfloat16_rn(f[j]);
        lo[j] = __float2bfloat16_rn(f[j] - __bfloat162float(hi[j]));
    }
    uint2 uh, ul;
    memcpy(&uh, hi, 8); memcpy(&ul, lo, 8);
    *reinterpret_cast<uint2*>(&dh[i4 * 4]) = uh;
    *reinterpret_cast<uint2*>(&dl[i4 * 4]) = ul;
}

// ---------------------------------------------------------------------------
// bf16x3 GEMM, pre-split inputs + cp.async double buffer, BK=32.
// mode 0: plain fp32 C store (+bias).
// mode 1: QKV fused epilogue — Q cols -> q_out fp32; K cols -> kh/kl bf16
//         hi/lo; V cols -> vh fp16 (768 = 6*128: one segment per block col).
// ---------------------------------------------------------------------------
#define AST2 40     // halves per A smem row (32 + 8 pad); 20 words % 32
#define BST2 136    // halves per B smem row (128 + 8 pad)

__global__ __launch_bounds__(256, 2)
void gemm_bf16x3_async_kernel(const __nv_bfloat16* __restrict__ Ah_g,
                              const __nv_bfloat16* __restrict__ Al_g,
                              const __nv_bfloat16* __restrict__ Bh_g,
                              const __nv_bfloat16* __restrict__ Bl_g,
                              const float* __restrict__ bias,
                              float* __restrict__ Cmat,
                              int M, int N, int K,
                              int mode,
                              float* __restrict__ q_out,
                              __nv_bfloat16* __restrict__ kh_out,
                              __nv_bfloat16* __restrict__ kl_out,
                              __half* __restrict__ vh_out)
{
    __shared__ __nv_bfloat16 Ah[2][128 * AST2];
    __shared__ __nv_bfloat16 Al[2][128 * AST2];
    __shared__ __nv_bfloat16 Bh[2][32 * BST2];
    __shared__ __nv_bfloat16 Bl[2][32 * BST2];

    const int tid  = threadIdx.x;
    const int warp = tid >> 5;
    const int lane = tid & 31;
    const int g    = lane >> 2;
    const int tg   = lane & 3;

    const int brow = blockIdx.y * 128;
    const int bcol = blockIdx.x * 128;
    const int wm   = (warp >> 2) * 64;
    const int wn   = (warp & 3) * 32;

    uint32_t sAh[2] = {(uint32_t)__cvta_generic_to_shared(Ah[0]),
                       (uint32_t)__cvta_generic_to_shared(Ah[1])};
    uint32_t sAl[2] = {(uint32_t)__cvta_generic_to_shared(Al[0]),
                       (uint32_t)__cvta_generic_to_shared(Al[1])};
    uint32_t sBh[2] = {(uint32_t)__cvta_generic_to_shared(Bh[0]),
                       (uint32_t)__cvta_generic_to_shared(Bh[1])};
    uint32_t sBl[2] = {(uint32_t)__cvta_generic_to_shared(Bl[0]),
                       (uint32_t)__cvta_generic_to_shared(Bl[1])};

    float acc[4][4][4];
    #pragma unroll
    for (int mt = 0; mt < 4; mt++)
        #pragma unroll
        for (int nt = 0; nt < 4; nt++)
            #pragma unroll
            for (int j = 0; j < 4; j++) acc[mt][nt][j] = 0.f;

    const int n_stages = K / 32;

    // Stage loader: A tile 128x32 halves (512 16B-chunks, column-major chunk
    // order for conflict-free STS phases), B tile 32x128 halves (512 chunks).
    auto issue = [&](int s, int buf) {
        const int k0 = s * 32;
        #pragma unroll
        for (int i = 0; i < 2; i++) {
            int c = i * 256 + tid;            // 0..511
            int ar = c & 127;                 // A row
            int ac = (c >> 7) * 8;            // A col (halves)
            cp_async16(sAh[buf] + (uint32_t)(ar * AST2 + ac) * 2u,
                       &Ah_g[(size_t)(brow + ar) * K + k0 + ac]);
            cp_async16(sAl[buf] + (uint32_t)(ar * AST2 + ac) * 2u,
                       &Al_g[(size_t)(brow + ar) * K + k0 + ac]);
            int br = c >> 4;                  // B row 0..31
            int bc = (c & 15) * 8;            // B col (halves)
            cp_async16(sBh[buf] + (uint32_t)(br * BST2 + bc) * 2u,
                       &Bh_g[(size_t)(k0 + br) * N + bcol + bc]);
            cp_async16(sBl[buf] + (uint32_t)(br * BST2 + bc) * 2u,
                       &Bl_g[(size_t)(k0 + br) * N + bcol + bc]);
        }
        cp_commit();
    };

    issue(0, 0);

    for (int s = 0; s < n_stages; s++) {
        const int buf = s & 1;
        if (s + 1 < n_stages) {
            issue(s + 1, buf ^ 1);
            asm volatile("cp.async.wait_group 1;");
        } else {
            asm volatile("cp.async.wait_group 0;");
        }
        __syncthreads();

        #pragma unroll
        for (int ks = 0; ks < 2; ks++) {
            uint32_t bhf[2][4], blf[2][4];
            #pragma unroll
            for (int ng = 0; ng < 2; ng++) {
                uint32_t boff = (uint32_t)(
                    (ks * 16 + (lane & 15)) * BST2 +
                    wn + ng * 16 + ((lane & 16) ? 8 : 0)) * 2u;
                ldmatrix_x4_trans(bhf[ng][0], bhf[ng][1], bhf[ng][2], bhf[ng][3],
                                  sBh[buf] + boff);
                ldmatrix_x4_trans(blf[ng][0], blf[ng][1], blf[ng][2], blf[ng][3],
                                  sBl[buf] + boff);
            }
            #pragma unroll
            for (int mt = 0; mt < 4; mt++) {
                uint32_t ahf[4], alf[4];
                uint32_t aoff = (uint32_t)(
                    (wm + mt * 16 + (lane & 15)) * AST2 +
                    ks * 16 + ((lane & 16) ? 8 : 0)) * 2u;
                ldmatrix_x4(ahf[0], ahf[1], ahf[2], ahf[3], sAh[buf] + aoff);
                ldmatrix_x4(alf[0], alf[1], alf[2], alf[3], sAl[buf] + aoff);
                #pragma unroll
                for (int ng = 0; ng < 2; ng++) {
                    #pragma unroll
                    for (int hh = 0; hh < 2; hh++) {
                        int nt = ng * 2 + hh;
                        uint32_t b0h = bhf[ng][2 * hh], b1h = bhf[ng][2 * hh + 1];
                        uint32_t b0l = blf[ng][2 * hh], b1l = blf[ng][2 * hh + 1];
                        mma_bf16(acc[mt][nt], ahf, b0h, b1h);
                        mma_bf16(acc[mt][nt], ahf, b0l, b1l);
                        mma_bf16(acc[mt][nt], alf, b0h, b1h);
                    }
                }
            }
        }
        __syncthreads();
    }

    if (mode == 0) {
        #pragma unroll
        for (int mt = 0; mt < 4; mt++) {
            #pragma unroll
            for (int nt = 0; nt < 4; nt++) {
                int row0 = brow + wm + mt * 16 + g;
                int col  = bcol + wn + nt * 8 + 2 * tg;
                float b0 = bias[col], b1 = bias[col + 1];
                float2 v0 = make_float2(acc[mt][nt][0] + b0, acc[mt][nt][1] + b1);
                float2 v1 = make_float2(acc[mt][nt][2] + b0, acc[mt][nt][3] + b1);
                *reinterpret_cast<float2*>(&Cmat[(size_t)row0 * N + col])       = v0;
                *reinterpret_cast<float2*>(&Cmat[(size_t)(row0 + 8) * N + col]) = v1;
            }
        }
    } else {
        const int seg = bcol / DMODEL;   // 0=Q, 1=K, 2=V (uniform per block)
        #pragma unroll
        for (int mt = 0; mt < 4; mt++) {
            #pragma unroll
            for (int nt = 0; nt < 4; nt++) {
                int row0  = brow + wm + mt * 16 + g;
                int colg  = bcol + wn + nt * 8 + 2 * tg;
                int colin = colg - seg * DMODEL;
                float b0 = bias[colg], b1 = bias[colg + 1];
                float fa0 = acc[mt][nt][0] + b0, fa1 = acc[mt][nt][1] + b1;
                float fb0 = acc[mt][nt][2] + b0, fb1 = acc[mt][nt][3] + b1;
                size_t d0 = (size_t)row0 * DMODEL + colin;
                size_t d1 = (size_t)(row0 + 8) * DMODEL + colin;
                if (seg == 0) {
                    *reinterpret_cast<float2*>(&q_out[d0]) = make_float2(fa0, fa1);
                    *reinterpret_cast<float2*>(&q_out[d1]) = make_float2(fb0, fb1);
                } else if (seg == 1) {
                    __nv_bfloat16 h0 = __float2bfloat16_rn(fa0);
                    __nv_bfloat16 h1 = __float2bfloat16_rn(fa1);
                    __nv_bfloat16 h2 = __float2bfloat16_rn(fb0);
                    __nv_bfloat16 h3 = __float2bfloat16_rn(fb1);
                    __nv_bfloat16 l0 = __float2bfloat16_rn(fa0 - __bfloat162float(h0));
                    __nv_bfloat16 l1 = __float2bfloat16_rn(fa1 - __bfloat162float(h1));
                    __nv_bfloat16 l2 = __float2bfloat16_rn(fb0 - __bfloat162float(h2));
                    __nv_bfloat16 l3 = __float2bfloat16_rn(fb1 - __bfloat162float(h3));
                    *reinterpret_cast<uint32_t*>(&kh_out[d0]) =
                        bf2_as_u32(__nv_bfloat162(h0, h1));
                    *reinterpret_cast<uint32_t*>(&kl_out[d0]) =
                        bf2_as_u32(__nv_bfloat162(l0, l1));
                    *reinterpret_cast<uint32_t*>(&kh_out[d1]) =
                        bf2_as_u32(__nv_bfloat162(h2, h3));
                    *reinterpret_cast<uint32_t*>(&kl_out[d1]) =
                        bf2_as_u32(__nv_bfloat162(l2, l3));
                } else {
                    *reinterpret_cast<uint32_t*>(&vh_out[d0]) =
                        h2_as_u32(__floats2half2_rn(fa0, fa1));
                    *reinterpret_cast<uint32_t*>(&vh_out[d1]) =
                        h2_as_u32(__floats2half2_rn(fb0, fb1));
                }
            }
        }
    }
}

// ---------------------------------------------------------------------------
// Tensor-core flash attention (causal), bf16x3 S-phase, pre-converted K/V.
// R8-proven shape: plain uint4 loads, static 27.6 KB smem, 128 threads,
// 64-key tiles, occupancy-based latency hiding.
// ---------------------------------------------------------------------------
#define KS 72        // halves per K smem row: 36 words % 32 == 4 -> clean
#define VSTRIDE 72   // halves per V row

__global__ __launch_bounds__(128)
void flash_attn_tc_kernel(const float* __restrict__ gq,
                          const __nv_bfloat16* __restrict__ gkh,
                          const __nv_bfloat16* __restrict__ gkl,
                          const __half* __restrict__ gvh,
                          __nv_bfloat16* __restrict__ outh,
                          __nv_bfloat16* __restrict__ outl)
{
    __shared__ __nv_bfloat16 Kh[64 * KS];
    __shared__ __nv_bfloat16 Kl[64 * KS];
    __shared__ __half        Vs[64][VSTRIDE];

    const int qt   = (int)gridDim.x - 1 - (int)blockIdx.x;  // heavy tiles first
    const int h    = blockIdx.y;
    const int b    = blockIdx.z;
    const int tid  = threadIdx.x;
    const int warp = tid >> 5;
    const int lane = tid & 31;
    const int g    = lane >> 2;
    const int tg   = lane & 3;

    const uint32_t sKh = (uint32_t)__cvta_generic_to_shared(Kh);
    const uint32_t sKl = (uint32_t)__cvta_generic_to_shared(Kl);

    const float qscale = 0.125f * 1.4426950408889634f;

    // --- Q fragments, bf16 hi/lo, m16n8k16 A layout ---
    uint32_t qh[4][4], ql[4][4];
    {
        const float* qbase =
            gq + (size_t)(b * SEQ + qt * 64 + warp * 16) * DMODEL + h * DHEAD;
        #pragma unroll
        for (int ks = 0; ks < 4; ks++) {
            #pragma unroll
            for (int j = 0; j < 4; j++) {
                int row = g + (j & 1) * 8;
                int col = ks * 16 + 2 * tg + (j & 2) * 4;
                float v0 = qbase[(size_t)row * DMODEL + col]     * qscale;
                float v1 = qbase[(size_t)row * DMODEL + col + 1] * qscale;
                __nv_bfloat16 h0 = __float2bfloat16_rn(v0);
                __nv_bfloat16 h1 = __float2bfloat16_rn(v1);
                __nv_bfloat16 l0 = __float2bfloat16_rn(v0 - __bfloat162float(h0));
                __nv_bfloat16 l1 = __float2bfloat16_rn(v1 - __bfloat162float(h1));
                qh[ks][j] = bf2_as_u32(__nv_bfloat162(h0, h1));
                ql[ks][j] = bf2_as_u32(__nv_bfloat162(l0, l1));
            }
        }
    }

    float oacc[8][4];
    #pragma unroll
    for (int dt = 0; dt < 8; dt++)
        #pragma unroll
        for (int j = 0; j < 4; j++) oacc[dt][j] = 0.f;

    float m0 = -1e30f, m1 = -1e30f, l0 = 0.f, l1 = 0.f;

    for (int kt = 0; kt <= qt; kt++) {
        __syncthreads();
        #pragma unroll
        for (int it = 0; it < 4; it++) {
            int idx = it * 128 + tid;
            int row = idx >> 3;
            int c8  = idx & 7;
            const size_t gidx =
                (size_t)(b * SEQ + kt * 64 + row) * DMODEL + h * DHEAD + c8 * 8;
            *reinterpret_cast<uint4*>(&Kh[row * KS + c8 * 8]) =
                *reinterpret_cast<const uint4*>(&gkh[gidx]);
            *reinterpret_cast<uint4*>(&Kl[row * KS + c8 * 8]) =
                *reinterpret_cast<const uint4*>(&gkl[gidx]);
            *reinterpret_cast<uint4*>(&Vs[row][c8 * 8]) =
                *reinterpret_cast<const uint4*>(&gvh[gidx]);
        }
        __syncthreads();

        // --- S = Qhi·Khi + Qhi·Klo + Qlo·Khi (bf16 k16 mma) ---
        float sacc[8][4];
        #pragma unroll
        for (int nt = 0; nt < 8; nt++)
            #pragma unroll
            for (int j = 0; j < 4; j++) sacc[nt][j] = 0.f;

        #pragma unroll
        for (int ks = 0; ks < 4; ks++) {
            #pragma unroll
            for (int ng = 0; ng < 4; ng++) {
                uint32_t boff = (uint32_t)(
                    (ng * 16 + (lane & 15)) * KS +
                    ks * 16 + ((lane & 16) ? 8 : 0)) * 2u;
                uint32_t bh0, bh1, bh2, bh3, bl0, bl1, bl2, bl3;
                ldmatrix_x4(bh0, bh1, bh2, bh3, sKh + boff);
                ldmatrix_x4(bl0, bl1, bl2, bl3, sKl + boff);
                mma_bf16(sacc[ng * 2],     qh[ks], bh0, bh2);
                mma_bf16(sacc[ng * 2],     qh[ks], bl0, bl2);
                mma_bf16(sacc[ng * 2],     ql[ks], bh0, bh2);
                mma_bf16(sacc[ng * 2 + 1], qh[ks], bh1, bh3);
                mma_bf16(sacc[ng * 2 + 1], qh[ks], bl1, bl3);
                mma_bf16(sacc[ng * 2 + 1], ql[ks], bh1, bh3);
            }
        }

        if (kt == qt) {
            #pragma unroll
            for (int nt = 0; nt < 8; nt++) {
                #pragma unroll
                for (int j = 0; j < 4; j++) {
                    int row = warp * 16 + g + (j >> 1) * 8;
                    int col = nt * 8 + 2 * tg + (j & 1);
                    if (col > row) sacc[nt][j] = -1e30f;
                }
            }
        }

        // --- online softmax (base-2) ---
        float mx0 = -1e30f, mx1 = -1e30f;
        #pragma unroll
        for (int nt = 0; nt < 8; nt++) {
            mx0 = fmaxf(mx0, fmaxf(sacc[nt][0], sacc[nt][1]));
            mx1 = fmaxf(mx1, fmaxf(sacc[nt][2], sacc[nt][3]));
        }
        mx0 = fmaxf(mx0, __shfl_xor_sync(0xffffffffu, mx0, 1));
        mx0 = fmaxf(mx0, __shfl_xor_sync(0xffffffffu, mx0, 2));
        mx1 = fmaxf(mx1, __shfl_xor_sync(0xffffffffu, mx1, 1));
        mx1 = fmaxf(mx1, __shfl_xor_sync(0xffffffffu, mx1, 2));

        float mn0 = fmaxf(m0, mx0);
        float mn1 = fmaxf(m1, mx1);
        float al0 = fast_exp2(m0 - mn0);
        float al1 = fast_exp2(m1 - mn1);

        float rs0 = 0.f, rs1 = 0.f;
        #pragma unroll
        for (int nt = 0; nt < 8; nt++) {
            float p0 = fast_exp2(sacc[nt][0] - mn0);
            float p1 = fast_exp2(sacc[nt][1] - mn0);
            float p2 = fast_exp2(sacc[nt][2] - mn1);
            float p3 = fast_exp2(sacc[nt][3] - mn1);
            sacc[nt][0] = p0; sacc[nt][1] = p1;
            sacc[nt][2] = p2; sacc[nt][3] = p3;
            rs0 += p0 + p1;
            rs1 += p2 + p3;
        }
        rs0 += __shfl_xor_sync(0xffffffffu, rs0, 1);
        rs0 += __shfl_xor_sync(0xffffffffu, rs0, 2);
        rs1 += __shfl_xor_sync(0xffffffffu, rs1, 1);
        rs1 += __shfl_xor_sync(0xffffffffu, rs1, 2);

        l0 = l0 * al0 + rs0;
        l1 = l1 * al1 + rs1;
        m0 = mn0;
        m1 = mn1;

        #pragma unroll
        for (int dt = 0; dt < 8; dt++) {
            oacc[dt][0] *= al0; oacc[dt][1] *= al0;
            oacc[dt][2] *= al1; oacc[dt][3] *= al1;
        }

        // --- O += P * V  (fp16 mma) ---
        #pragma unroll
        for (int ks = 0; ks < 4; ks++) {
            uint32_t pa[4];
            pa[0] = h2_as_u32(__floats2half2_rn(sacc[2*ks][0],   sacc[2*ks][1]));
            pa[1] = h2_as_u32(__floats2half2_rn(sacc[2*ks][2],   sacc[2*ks][3]));
            pa[2] = h2_as_u32(__floats2half2_rn(sacc[2*ks+1][0], sacc[2*ks+1][1]));
            pa[3] = h2_as_u32(__floats2half2_rn(sacc[2*ks+1][2], sacc[2*ks+1][3]));
            #pragma unroll
            for (int dp = 0; dp < 4; dp++) {
                int krow = ks * 16 + (lane & 15);
                int col  = dp * 16 + ((lane & 16) ? 8 : 0);
                uint32_t addr = (uint32_t)__cvta_generic_to_shared(&Vs[krow][col]);
                uint32_t b0, b1, b2, b3;
                ldmatrix_x4_trans(b0, b1, b2, b3, addr);
                mma_f16(oacc[2 * dp],     pa, b0, b1);
                mma_f16(oacc[2 * dp + 1], pa, b2, b3);
            }
        }
    }

    // --- normalize + write directly as bf16 hi/lo ---
    const float inv0 = 1.f / l0;
    const float inv1 = 1.f / l1;
    const size_t obase =
        (size_t)(b * SEQ + qt * 64 + warp * 16) * DMODEL + h * DHEAD;
    #pragma unroll
    for (int dt = 0; dt < 8; dt++) {
        int col = dt * 8 + 2 * tg;
        float f[4] = {oacc[dt][0] * inv0, oacc[dt][1] * inv0,
                      oacc[dt][2] * inv1, oacc[dt][3] * inv1};
        __nv_bfloat16 hi[4], lo[4];
        #pragma unroll
        for (int j = 0; j < 4; j++) {
            hi[j] = __float2bfloat16_rn(f[j]);
            lo[j] = __float2bfloat16_rn(f[j] - __bfloat162float(hi[j]));
        }
        size_t i0 = obase + (size_t)g * DMODEL + col;
        size_t i1 = obase + (size_t)(g + 8) * DMODEL + col;
        *reinterpret_cast<uint32_t*>(&outh[i0]) =
            bf2_as_u32(__nv_bfloat162(hi[0], hi[1]));
        *reinterpret_cast<uint32_t*>(&outl[i0]) =
            bf2_as_u32(__nv_bfloat162(lo[0], lo[1]));
        *reinterpret_cast<uint32_t*>(&outh[i1]) =
            bf2_as_u32(__nv_bfloat162(hi[2], hi[3]));
        *reinterpret_cast<uint32_t*>(&outl[i1]) =
            bf2_as_u32(__nv_bfloat162(lo[2], lo[3]));
    }
}

// ---------------------------------------------------------------------------
// Launch
// ---------------------------------------------------------------------------
extern "C" void kernel_launch(void* const* d_in, const int* in_sizes, int n_in,
                              void* d_out, int out_size)
{
    const float* x      = (const float*)d_in[0];
    const float* W_qkv  = (const float*)d_in[1];
    const float* b_qkv  = (const float*)d_in[2];
    const float* W_proj = (const float*)d_in[3];
    const float* b_proj = (const float*)d_in[4];
    float* out = (float*)d_out;

    void *p_q, *p_xh, *p_xl, *p_wqh, *p_wql, *p_wph, *p_wpl;
    void *p_ath, *p_atl, *p_kh, *p_kl, *p_vh;
    cudaGetSymbolAddress(&p_q, g_q);
    cudaGetSymbolAddress(&p_xh, g_xh);   cudaGetSymbolAddress(&p_xl, g_xl);
    cudaGetSymbolAddress(&p_wqh, g_wqh); cudaGetSymbolAddress(&p_wql, g_wql);
    cudaGetSymbolAddress(&p_wph, g_wph); cudaGetSymbolAddress(&p_wpl, g_wpl);
    cudaGetSymbolAddress(&p_ath, g_ath); cudaGetSymbolAddress(&p_atl, g_atl);
    cudaGetSymbolAddress(&p_kh, g_kh);   cudaGetSymbolAddress(&p_kl, g_kl);
    cudaGetSymbolAddress(&p_vh, g_vh);

    float* gq = (float*)p_q;
    __nv_bfloat16 *xh = (__nv_bfloat16*)p_xh,  *xl = (__nv_bfloat16*)p_xl;
    __nv_bfloat16 *wqh = (__nv_bfloat16*)p_wqh, *wql = (__nv_bfloat16*)p_wql;
    __nv_bfloat16 *wph = (__nv_bfloat16*)p_wph, *wpl = (__nv_bfloat16*)p_wpl;
    __nv_bfloat16 *ath = (__nv_bfloat16*)p_ath, *atl = (__nv_bfloat16*)p_atl;
    __nv_bfloat16 *kh = (__nv_bfloat16*)p_kh,   *kl = (__nv_bfloat16*)p_kl;
    __half *vh = (__half*)p_vh;

    // 0) Pre-split GEMM inputs (streaming)
    split32_kernel<<<BT * DMODEL / 4 / 256, 256>>>(x, xh, xl);
    split32_kernel<<<DMODEL * C3 / 4 / 256, 256>>>(W_qkv, wqh, wql);
    split32_kernel<<<DMODEL * DMODEL / 4 / 256, 256>>>(W_proj, wph, wpl);

    // 1) QKV projection; fused epilogue writes Q fp32, K bf16 hi/lo, V fp16
    {
        dim3 grid(C3 / 128, BT / 128);
        gemm_bf16x3_async_kernel<<<grid, 256>>>(xh, xl, wqh, wql, b_qkv,
                                                nullptr, BT, C3, DMODEL,
                                                1, gq, kh, kl, vh);
    }

    // 2) Causal flash attention (R8 shape); writes att bf16 hi/lo
    {
        dim3 grid(SEQ / 64, NHEADS, BATCH);
        flash_attn_tc_kernel<<<grid, 128>>>(gq, kh, kl, vh, ath, atl);
    }

    // 3) Output projection (plain fp32 epilogue)
    {
        dim3 grid(DMODEL / 128, BT / 128);
        gemm_bf16x3_async_kernel<<<grid, 256>>>(ath, atl, wph, wpl, b_proj,
                                                out, BT, DMODEL, DMODEL,
                                                0, nullptr, nullptr, nullptr,
                                                nullptr);
    }
}

// round 13
// speedup vs baseline: 2.7422x; 2.7422x over previous
#include <cuda_runtime.h>
#include <cuda_fp16.h>
#include <cuda_bf16.h>
#include <math_constants.h>
#include <cstdint>
#include <cstring>

// Problem constants (fixed by reference setup_inputs)
#define BATCH   2
#define SEQ     4096
#define DMODEL  768
#define NHEADS  12
#define DHEAD   64
#define BT      (BATCH * SEQ)        // 8192
#define C3      (3 * DMODEL)         // 2304

// Scratch (device globals: allocation-free per harness rules)
__device__ __half g_x16[(size_t)BT * DMODEL];      // x fp16
__device__ __half g_wq16[(size_t)DMODEL * C3];     // W_qkv fp16
__device__ __half g_wp16[(size_t)DMODEL * DMODEL]; // W_proj fp16
__device__ __half g_q16[(size_t)BT * DMODEL];      // Q fp16
__device__ __half g_k16[(size_t)BT * DMODEL];      // K fp16
__device__ __half g_v16[(size_t)BT * DMODEL];      // V fp16
__device__ __half g_at16[(size_t)BT * DMODEL];     // att out fp16

// ---------------------------------------------------------------------------
// PTX helpers
// ---------------------------------------------------------------------------
__device__ __forceinline__ float fast_exp2(float x) {
    float y;
    asm("ex2.approx.f32 %0, %1;" : "=f"(y) : "f"(x));
    return y;
}

__device__ __forceinline__ uint32_t h2_as_u32(__half2 h) {
    uint32_t r; memcpy(&r, &h, 4); return r;
}
__device__ __forceinline__ __half2 u32_as_h2(uint32_t r) {
    __half2 h; memcpy(&h, &r, 4); return h;
}

__device__ __forceinline__ void mma_f16(float c[4], const uint32_t a[4],
                                        uint32_t b0, uint32_t b1) {
    asm volatile(
        "mma.sync.aligned.m16n8k16.row.col.f32.f16.f16.f32 "
        "{%0,%1,%2,%3},{%4,%5,%6,%7},{%8,%9},{%0,%1,%2,%3};"
        : "+f"(c[0]), "+f"(c[1]), "+f"(c[2]), "+f"(c[3])
        : "r"(a[0]), "r"(a[1]), "r"(a[2]), "r"(a[3]), "r"(b0), "r"(b1));
}

__device__ __forceinline__ void ldmatrix_x4(uint32_t& r0, uint32_t& r1,
                                            uint32_t& r2, uint32_t& r3,
                                            uint32_t addr) {
    asm volatile(
        "ldmatrix.sync.aligned.m8n8.x4.shared.b16 {%0,%1,%2,%3}, [%4];"
        : "=r"(r0), "=r"(r1), "=r"(r2), "=r"(r3)
        : "r"(addr));
}

__device__ __forceinline__ void ldmatrix_x4_trans(uint32_t& r0, uint32_t& r1,
                                                  uint32_t& r2, uint32_t& r3,
                                                  uint32_t addr) {
    asm volatile(
        "ldmatrix.sync.aligned.m8n8.x4.trans.shared.b16 {%0,%1,%2,%3}, [%4];"
        : "=r"(r0), "=r"(r1), "=r"(r2), "=r"(r3)
        : "r"(addr));
}

__device__ __forceinline__ void cp_async16(uint32_t smem, const void* gmem) {
    asm volatile("cp.async.cg.shared.global [%0], [%1], 16;"
                 :: "r"(smem), "l"(gmem));
}
__device__ __forceinline__ void cp_commit() {
    asm volatile("cp.async.commit_group;");
}

// ---------------------------------------------------------------------------
// fp32 -> fp16 convert (streaming). One thread per float4.
// ---------------------------------------------------------------------------
__global__ __launch_bounds__(256)
void cvt16_kernel(const float* __restrict__ src, __half* __restrict__ dst)
{
    const size_t i4 = (size_t)blockIdx.x * 256 + threadIdx.x;
    float4 v = reinterpret_cast<const float4*>(src)[i4];
    __half h[4] = {__float2half_rn(v.x), __float2half_rn(v.y),
                   __float2half_rn(v.z), __float2half_rn(v.w)};
    uint2 u;
    memcpy(&u, h, 8);
    *reinterpret_cast<uint2*>(&dst[i4 * 4]) = u;
}

// ---------------------------------------------------------------------------
// fp16 GEMM (fp32 accum), cp.async double buffer, BK=16 (proven R9 shape).
// mode 0: fp32 C store (+bias).
// mode 1: QKV fused epilogue — writes Q/K/V segments directly as fp16
//         (+bias). 768 = 6*128: each 128-col block is in one segment.
// ---------------------------------------------------------------------------
#define AST2 24     // halves per A smem row (16 + 8 pad); conflict-free
#define BST2 136    // halves per B smem row (128 + 8 pad)

__global__ __launch_bounds__(256, 2)
void gemm_f16_async_kernel(const __half* __restrict__ A16,
                           const __half* __restrict__ B16,
                           const float* __restrict__ bias,
                           float* __restrict__ Cmat,
                           int M, int N, int K,
                           int mode,
                           __half* __restrict__ q_out,
                           __half* __restrict__ k_out,
                           __half* __restrict__ v_out)
{
    __shared__ __half As[2][128 * AST2];
    __shared__ __half Bs[2][16 * BST2];

    const int tid  = threadIdx.x;
    const int warp = tid >> 5;
    const int lane = tid & 31;
    const int g    = lane >> 2;
    const int tg   = lane & 3;

    const int brow = blockIdx.y * 128;
    const int bcol = blockIdx.x * 128;
    const int wm   = (warp >> 2) * 64;
    const int wn   = (warp & 3) * 32;

    uint32_t sA[2] = {(uint32_t)__cvta_generic_to_shared(As[0]),
                      (uint32_t)__cvta_generic_to_shared(As[1])};
    uint32_t sB[2] = {(uint32_t)__cvta_generic_to_shared(Bs[0]),
                      (uint32_t)__cvta_generic_to_shared(Bs[1])};

    const int a_row = tid >> 1;          // 0..127
    const int a_c   = (tid & 1) * 8;     // halves 0 or 8
    const int b_row = tid >> 4;          // 0..15
    const int b_c   = (tid & 15) * 8;    // 0..120

    float acc[4][4][4];
    #pragma unroll
    for (int mt = 0; mt < 4; mt++)
        #pragma unroll
        for (int nt = 0; nt < 4; nt++)
            #pragma unroll
            for (int j = 0; j < 4; j++) acc[mt][nt][j] = 0.f;

    const int n_stages = K / 16;

    auto issue = [&](int s, int buf) {
        const int k0 = s * 16;
        cp_async16(sA[buf] + (a_row * AST2 + a_c) * 2,
                   &A16[(size_t)(brow + a_row) * K + k0 + a_c]);
        cp_async16(sB[buf] + (b_row * BST2 + b_c) * 2,
                   &B16[(size_t)(k0 + b_row) * N + bcol + b_c]);
        cp_commit();
    };

    issue(0, 0);

    for (int s = 0; s < n_stages; s++) {
        const int buf = s & 1;
        if (s + 1 < n_stages) {
            issue(s + 1, buf ^ 1);
            asm volatile("cp.async.wait_group 1;");
        } else {
            asm volatile("cp.async.wait_group 0;");
        }
        __syncthreads();

        uint32_t bf[2][4];
        #pragma unroll
        for (int ng = 0; ng < 2; ng++) {
            uint32_t boff = (uint32_t)(
                (lane & 15) * BST2 + wn + ng * 16 + ((lane & 16) ? 8 : 0)) * 2u;
            ldmatrix_x4_trans(bf[ng][0], bf[ng][1], bf[ng][2], bf[ng][3],
                              sB[buf] + boff);
        }
        #pragma unroll
        for (int mt = 0; mt < 4; mt++) {
            uint32_t af[4];
            uint32_t aoff = (uint32_t)(
                (wm + mt * 16 + (lane & 15)) * AST2 + ((lane & 16) ? 8 : 0)) * 2u;
            ldmatrix_x4(af[0], af[1], af[2], af[3], sA[buf] + aoff);
            #pragma unroll
            for (int ng = 0; ng < 2; ng++) {
                #pragma unroll
                for (int hh = 0; hh < 2; hh++) {
                    mma_f16(acc[mt][ng * 2 + hh], af,
                            bf[ng][2 * hh], bf[ng][2 * hh + 1]);
                }
            }
        }
        __syncthreads();
    }

    if (mode == 0) {
        #pragma unroll
        for (int mt = 0; mt < 4; mt++) {
            #pragma unroll
            for (int nt = 0; nt < 4; nt++) {
                int row0 = brow + wm + mt * 16 + g;
                int col  = bcol + wn + nt * 8 + 2 * tg;
                float b0 = bias[col], b1 = bias[col + 1];
                float2 v0 = make_float2(acc[mt][nt][0] + b0, acc[mt][nt][1] + b1);
                float2 v1 = make_float2(acc[mt][nt][2] + b0, acc[mt][nt][3] + b1);
                *reinterpret_cast<float2*>(&Cmat[(size_t)row0 * N + col])       = v0;
                *reinterpret_cast<float2*>(&Cmat[(size_t)(row0 + 8) * N + col]) = v1;
            }
        }
    } else {
        const int seg = bcol / DMODEL;   // 0=Q, 1=K, 2=V (uniform per block)
        __half* dst = (seg == 0) ? q_out : (seg == 1) ? k_out : v_out;
        #pragma unroll
        for (int mt = 0; mt < 4; mt++) {
            #pragma unroll
            for (int nt = 0; nt < 4; nt++) {
                int row0  = brow + wm + mt * 16 + g;
                int colg  = bcol + wn + nt * 8 + 2 * tg;
                int colin = colg - seg * DMODEL;
                float b0 = bias[colg], b1 = bias[colg + 1];
                float fa0 = acc[mt][nt][0] + b0, fa1 = acc[mt][nt][1] + b1;
                float fb0 = acc[mt][nt][2] + b0, fb1 = acc[mt][nt][3] + b1;
                size_t d0 = (size_t)row0 * DMODEL + colin;
                size_t d1 = (size_t)(row0 + 8) * DMODEL + colin;
                *reinterpret_cast<uint32_t*>(&dst[d0]) =
                    h2_as_u32(__floats2half2_rn(fa0, fa1));
                *reinterpret_cast<uint32_t*>(&dst[d1]) =
                    h2_as_u32(__floats2half2_rn(fb0, fb1));
            }
        }
    }
}

// ---------------------------------------------------------------------------
// Tensor-core flash attention (causal), fp16 S (1 mma term) + fp16 PV.
// R8-proven shape: plain uint4 loads, static smem (18.4 KB), 128 threads,
// 64-key tiles, occupancy-based latency hiding.
// ---------------------------------------------------------------------------
#define KS 72        // halves per K smem row: 36 words % 32 == 4 -> clean
#define VSTRIDE 72   // halves per V row

__global__ __launch_bounds__(128)
void flash_attn_tc_kernel(const __half* __restrict__ gq,
                          const __half* __restrict__ gk,
                          const __half* __restrict__ gv,
                          __half* __restrict__ outa)
{
    __shared__ __half Kh[64 * KS];
    __shared__ __half Vs[64][VSTRIDE];

    const int qt   = (int)gridDim.x - 1 - (int)blockIdx.x;  // heavy tiles first
    const int h    = blockIdx.y;
    const int b    = blockIdx.z;
    const int tid  = threadIdx.x;
    const int warp = tid >> 5;
    const int lane = tid & 31;
    const int g    = lane >> 2;
    const int tg   = lane & 3;

    const uint32_t sKh = (uint32_t)__cvta_generic_to_shared(Kh);

    // Fold softmax scale and log2(e) into Q (softmax scale-invariant).
    const float qscale = 0.125f * 1.4426950408889634f;

    // --- Q fragments, fp16, m16n8k16 A layout; scale folded in ---
    uint32_t qf[4][4];
    {
        const __half* qbase =
            gq + (size_t)(b * SEQ + qt * 64 + warp * 16) * DMODEL + h * DHEAD;
        #pragma unroll
        for (int ks = 0; ks < 4; ks++) {
            #pragma unroll
            for (int j = 0; j < 4; j++) {
                int row = g + (j & 1) * 8;
                int col = ks * 16 + 2 * tg + (j & 2) * 4;
                uint32_t raw = *reinterpret_cast<const uint32_t*>(
                    &qbase[(size_t)row * DMODEL + col]);
                float2 f = __half22float2(u32_as_h2(raw));
                qf[ks][j] = h2_as_u32(
                    __floats2half2_rn(f.x * qscale, f.y * qscale));
            }
        }
    }

    float oacc[8][4];
    #pragma unroll
    for (int dt = 0; dt < 8; dt++)
        #pragma unroll
        for (int j = 0; j < 4; j++) oacc[dt][j] = 0.f;

    float m0 = -1e30f, m1 = -1e30f, l0 = 0.f, l1 = 0.f;

    for (int kt = 0; kt <= qt; kt++) {
        __syncthreads();
        // Cooperative copy of K and V tiles (uint4)
        #pragma unroll
        for (int it = 0; it < 4; it++) {
            int idx = it * 128 + tid;       // 0..511
            int row = idx >> 3;             // key 0..63
            int c8  = idx & 7;              // 8-half group
            const size_t gidx =
                (size_t)(b * SEQ + kt * 64 + row) * DMODEL + h * DHEAD + c8 * 8;
            *reinterpret_cast<uint4*>(&Kh[row * KS + c8 * 8]) =
                *reinterpret_cast<const uint4*>(&gk[gidx]);
            *reinterpret_cast<uint4*>(&Vs[row][c8 * 8]) =
                *reinterpret_cast<const uint4*>(&gv[gidx]);
        }
        __syncthreads();

        // --- S = Q·K^T (fp16 mma, 1 term) ---
        // ldmatrix non-trans on [key][d]: r0=(n0-7,k0-7) r1=(n8-15,k0-7)
        //                                 r2=(n0-7,k8-15) r3=(n8-15,k8-15)
        float sacc[8][4];
        #pragma unroll
        for (int nt = 0; nt < 8; nt++)
            #pragma unroll
            for (int j = 0; j < 4; j++) sacc[nt][j] = 0.f;

        #pragma unroll
        for (int ks = 0; ks < 4; ks++) {
            #pragma unroll
            for (int ng = 0; ng < 4; ng++) {
                uint32_t boff = (uint32_t)(
                    (ng * 16 + (lane & 15)) * KS +
                    ks * 16 + ((lane & 16) ? 8 : 0)) * 2u;
                uint32_t b0, b1, b2, b3;
                ldmatrix_x4(b0, b1, b2, b3, sKh + boff);
                mma_f16(sacc[ng * 2],     qf[ks], b0, b2);
                mma_f16(sacc[ng * 2 + 1], qf[ks], b1, b3);
            }
        }

        // --- causal mask on diagonal tile ---
        if (kt == qt) {
            #pragma unroll
            for (int nt = 0; nt < 8; nt++) {
                #pragma unroll
                for (int j = 0; j < 4; j++) {
                    int row = warp * 16 + g + (j >> 1) * 8;
                    int col = nt * 8 + 2 * tg + (j & 1);
                    if (col > row) sacc[nt][j] = -1e30f;
                }
            }
        }

        // --- online softmax (base-2) ---
        float mx0 = -1e30f, mx1 = -1e30f;
        #pragma unroll
        for (int nt = 0; nt < 8; nt++) {
            mx0 = fmaxf(mx0, fmaxf(sacc[nt][0], sacc[nt][1]));
            mx1 = fmaxf(mx1, fmaxf(sacc[nt][2], sacc[nt][3]));
        }
        mx0 = fmaxf(mx0, __shfl_xor_sync(0xffffffffu, mx0, 1));
        mx0 = fmaxf(mx0, __shfl_xor_sync(0xffffffffu, mx0, 2));
        mx1 = fmaxf(mx1, __shfl_xor_sync(0xffffffffu, mx1, 1));
        mx1 = fmaxf(mx1, __shfl_xor_sync(0xffffffffu, mx1, 2));

        float mn0 = fmaxf(m0, mx0);
        float mn1 = fmaxf(m1, mx1);
        float al0 = fast_exp2(m0 - mn0);
        float al1 = fast_exp2(m1 - mn1);

        float rs0 = 0.f, rs1 = 0.f;
        #pragma unroll
        for (int nt = 0; nt < 8; nt++) {
            float p0 = fast_exp2(sacc[nt][0] - mn0);
            float p1 = fast_exp2(sacc[nt][1] - mn0);
            float p2 = fast_exp2(sacc[nt][2] - mn1);
            float p3 = fast_exp2(sacc[nt][3] - mn1);
            sacc[nt][0] = p0; sacc[nt][1] = p1;
            sacc[nt][2] = p2; sacc[nt][3] = p3;
            rs0 += p0 + p1;
            rs1 += p2 + p3;
        }
        rs0 += __shfl_xor_sync(0xffffffffu, rs0, 1);
        rs0 += __shfl_xor_sync(0xffffffffu, rs0, 2);
        rs1 += __shfl_xor_sync(0xffffffffu, rs1, 1);
        rs1 += __shfl_xor_sync(0xffffffffu, rs1, 2);

        l0 = l0 * al0 + rs0;
        l1 = l1 * al1 + rs1;
        m0 = mn0;
        m1 = mn1;

        #pragma unroll
        for (int dt = 0; dt < 8; dt++) {
            oacc[dt][0] *= al0; oacc[dt][1] *= al0;
            oacc[dt][2] *= al1; oacc[dt][3] *= al1;
        }

        // --- O += P * V  (fp16 mma) ---
        #pragma unroll
        for (int ks = 0; ks < 4; ks++) {
            uint32_t pa[4];
            pa[0] = h2_as_u32(__floats2half2_rn(sacc[2*ks][0],   sacc[2*ks][1]));
            pa[1] = h2_as_u32(__floats2half2_rn(sacc[2*ks][2],   sacc[2*ks][3]));
            pa[2] = h2_as_u32(__floats2half2_rn(sacc[2*ks+1][0], sacc[2*ks+1][1]));
            pa[3] = h2_as_u32(__floats2half2_rn(sacc[2*ks+1][2], sacc[2*ks+1][3]));
            #pragma unroll
            for (int dp = 0; dp < 4; dp++) {
                int krow = ks * 16 + (lane & 15);
                int col  = dp * 16 + ((lane & 16) ? 8 : 0);
                uint32_t addr = (uint32_t)__cvta_generic_to_shared(&Vs[krow][col]);
                uint32_t b0, b1, b2, b3;
                ldmatrix_x4_trans(b0, b1, b2, b3, addr);
                mma_f16(oacc[2 * dp],     pa, b0, b1);
                mma_f16(oacc[2 * dp + 1], pa, b2, b3);
            }
        }
    }

    // --- normalize + write fp16 ---
    const float inv0 = 1.f / l0;
    const float inv1 = 1.f / l1;
    const size_t obase =
        (size_t)(b * SEQ + qt * 64 + warp * 16) * DMODEL + h * DHEAD;
    #pragma unroll
    for (int dt = 0; dt < 8; dt++) {
        int col = dt * 8 + 2 * tg;
        size_t i0 = obase + (size_t)g * DMODEL + col;
        size_t i1 = obase + (size_t)(g + 8) * DMODEL + col;
        *reinterpret_cast<uint32_t*>(&outa[i0]) = h2_as_u32(
            __floats2half2_rn(oacc[dt][0] * inv0, oacc[dt][1] * inv0));
        *reinterpret_cast<uint32_t*>(&outa[i1]) = h2_as_u32(
            __floats2half2_rn(oacc[dt][2] * inv1, oacc[dt][3] * inv1));
    }
}

// ---------------------------------------------------------------------------
// Launch
// ---------------------------------------------------------------------------
extern "C" void kernel_launch(void* const* d_in, const int* in_sizes, int n_in,
                              void* d_out, int out_size)
{
    const float* x      = (const float*)d_in[0];
    const float* W_qkv  = (const float*)d_in[1];
    const float* b_qkv  = (const float*)d_in[2];
    const float* W_proj = (const float*)d_in[3];
    const float* b_proj = (const float*)d_in[4];
    float* out = (float*)d_out;

    void *p_x16, *p_wq16, *p_wp16, *p_q16, *p_k16, *p_v16, *p_at16;
    cudaGetSymbolAddress(&p_x16, g_x16);
    cudaGetSymbolAddress(&p_wq16, g_wq16);
    cudaGetSymbolAddress(&p_wp16, g_wp16);
    cudaGetSymbolAddress(&p_q16, g_q16);
    cudaGetSymbolAddress(&p_k16, g_k16);
    cudaGetSymbolAddress(&p_v16, g_v16);
    cudaGetSymbolAddress(&p_at16, g_at16);

    __half* x16  = (__half*)p_x16;
    __half* wq16 = (__half*)p_wq16;
    __half* wp16 = (__half*)p_wp16;
    __half* q16  = (__half*)p_q16;
    __half* k16  = (__half*)p_k16;
    __half* v16  = (__half*)p_v16;
    __half* at16 = (__half*)p_at16;

    // 0) fp32 -> fp16 input converts (streaming)
    cvt16_kernel<<<BT * DMODEL / 4 / 256, 256>>>(x, x16);
    cvt16_kernel<<<DMODEL * C3 / 4 / 256, 256>>>(W_qkv, wq16);
    cvt16_kernel<<<DMODEL * DMODEL / 4 / 256, 256>>>(W_proj, wp16);

    // 1) QKV projection (fp16 mma); fused epilogue writes Q/K/V fp16
    {
        dim3 grid(C3 / 128, BT / 128);
        gemm_f16_async_kernel<<<grid, 256>>>(x16, wq16, b_qkv,
                                             nullptr, BT, C3, DMODEL,
                                             1, q16, k16, v16);
    }

    // 2) Causal flash attention (fp16 S + fp16 PV); writes att fp16
    {
        dim3 grid(SEQ / 64, NHEADS, BATCH);
        flash_attn_tc_kernel<<<grid, 128>>>(q16, k16, v16, at16);
    }

    // 3) Output projection (fp16 mma, fp32 epilogue + bias)
    {
        dim3 grid(DMODEL / 128, BT / 128);
        gemm_f16_async_kernel<<<grid, 256>>>(at16, wp16, b_proj,
                                             out, BT, DMODEL, DMODEL,
                                             0, nullptr, nullptr, nullptr);
    }
}

// round 14
// speedup vs baseline: 2.9315x; 1.0690x over previous
#include <cuda_runtime.h>
#include <cuda_fp16.h>
#include <cuda_bf16.h>
#include <math_constants.h>
#include <cstdint>
#include <cstring>

// Problem constants (fixed by reference setup_inputs)
#define BATCH   2
#define SEQ     4096
#define DMODEL  768
#define NHEADS  12
#define DHEAD   64
#define BT      (BATCH * SEQ)        // 8192
#define C3      (3 * DMODEL)         // 2304

// Scratch (device globals: allocation-free per harness rules)
__device__ __half g_x16[(size_t)BT * DMODEL];      // x fp16
__device__ __half g_wq16[(size_t)DMODEL * C3];     // W_qkv fp16
__device__ __half g_wp16[(size_t)DMODEL * DMODEL]; // W_proj fp16
__device__ __half g_q16[(size_t)BT * DMODEL];      // Q fp16
__device__ __half g_k16[(size_t)BT * DMODEL];      // K fp16
__device__ __half g_v16[(size_t)BT * DMODEL];      // V fp16
__device__ __half g_at16[(size_t)BT * DMODEL];     // att out fp16

// ---------------------------------------------------------------------------
// PTX helpers
// ---------------------------------------------------------------------------
__device__ __forceinline__ float fast_exp2(float x) {
    float y;
    asm("ex2.approx.f32 %0, %1;" : "=f"(y) : "f"(x));
    return y;
}

__device__ __forceinline__ uint32_t h2_as_u32(__half2 h) {
    uint32_t r; memcpy(&r, &h, 4); return r;
}
__device__ __forceinline__ __half2 u32_as_h2(uint32_t r) {
    __half2 h; memcpy(&h, &r, 4); return h;
}

__device__ __forceinline__ void mma_f16(float c[4], const uint32_t a[4],
                                        uint32_t b0, uint32_t b1) {
    asm volatile(
        "mma.sync.aligned.m16n8k16.row.col.f32.f16.f16.f32 "
        "{%0,%1,%2,%3},{%4,%5,%6,%7},{%8,%9},{%0,%1,%2,%3};"
        : "+f"(c[0]), "+f"(c[1]), "+f"(c[2]), "+f"(c[3])
        : "r"(a[0]), "r"(a[1]), "r"(a[2]), "r"(a[3]), "r"(b0), "r"(b1));
}

__device__ __forceinline__ void ldmatrix_x4(uint32_t& r0, uint32_t& r1,
                                            uint32_t& r2, uint32_t& r3,
                                            uint32_t addr) {
    asm volatile(
        "ldmatrix.sync.aligned.m8n8.x4.shared.b16 {%0,%1,%2,%3}, [%4];"
        : "=r"(r0), "=r"(r1), "=r"(r2), "=r"(r3)
        : "r"(addr));
}

__device__ __forceinline__ void ldmatrix_x4_trans(uint32_t& r0, uint32_t& r1,
                                                  uint32_t& r2, uint32_t& r3,
                                                  uint32_t addr) {
    asm volatile(
        "ldmatrix.sync.aligned.m8n8.x4.trans.shared.b16 {%0,%1,%2,%3}, [%4];"
        : "=r"(r0), "=r"(r1), "=r"(r2), "=r"(r3)
        : "r"(addr));
}

__device__ __forceinline__ void cp_async16(uint32_t smem, const void* gmem) {
    asm volatile("cp.async.cg.shared.global [%0], [%1], 16;"
                 :: "r"(smem), "l"(gmem));
}
__device__ __forceinline__ void cp_commit() {
    asm volatile("cp.async.commit_group;");
}

// ---------------------------------------------------------------------------
// fp32 -> fp16 convert (streaming). One thread per float4.
// ---------------------------------------------------------------------------
__global__ __launch_bounds__(256)
void cvt16_kernel(const float* __restrict__ src, __half* __restrict__ dst)
{
    const size_t i4 = (size_t)blockIdx.x * 256 + threadIdx.x;
    float4 v = reinterpret_cast<const float4*>(src)[i4];
    __half h[4] = {__float2half_rn(v.x), __float2half_rn(v.y),
                   __float2half_rn(v.z), __float2half_rn(v.w)};
    uint2 u;
    memcpy(&u, h, 8);
    *reinterpret_cast<uint2*>(&dst[i4 * 4]) = u;
}

// ---------------------------------------------------------------------------
// fp16 GEMM (fp32 accum), cp.async double buffer, BK=16 (proven R13 shape).
// mode 0: fp32 C store (+bias).
// mode 1: QKV fused epilogue — writes Q/K/V segments directly as fp16.
// ---------------------------------------------------------------------------
#define AST2 24     // halves per A smem row (16 + 8 pad); conflict-free
#define BST2 136    // halves per B smem row (128 + 8 pad)

__global__ __launch_bounds__(256, 2)
void gemm_f16_async_kernel(const __half* __restrict__ A16,
                           const __half* __restrict__ B16,
                           const float* __restrict__ bias,
                           float* __restrict__ Cmat,
                           int M, int N, int K,
                           int mode,
                           __half* __restrict__ q_out,
                           __half* __restrict__ k_out,
                           __half* __restrict__ v_out)
{
    __shared__ __half As[2][128 * AST2];
    __shared__ __half Bs[2][16 * BST2];

    const int tid  = threadIdx.x;
    const int warp = tid >> 5;
    const int lane = tid & 31;
    const int g    = lane >> 2;
    const int tg   = lane & 3;

    const int brow = blockIdx.y * 128;
    const int bcol = blockIdx.x * 128;
    const int wm   = (warp >> 2) * 64;
    const int wn   = (warp & 3) * 32;

    uint32_t sA[2] = {(uint32_t)__cvta_generic_to_shared(As[0]),
                      (uint32_t)__cvta_generic_to_shared(As[1])};
    uint32_t sB[2] = {(uint32_t)__cvta_generic_to_shared(Bs[0]),
                      (uint32_t)__cvta_generic_to_shared(Bs[1])};

    const int a_row = tid >> 1;          // 0..127
    const int a_c   = (tid & 1) * 8;     // halves 0 or 8
    const int b_row = tid >> 4;          // 0..15
    const int b_c   = (tid & 15) * 8;    // 0..120

    float acc[4][4][4];
    #pragma unroll
    for (int mt = 0; mt < 4; mt++)
        #pragma unroll
        for (int nt = 0; nt < 4; nt++)
            #pragma unroll
            for (int j = 0; j < 4; j++) acc[mt][nt][j] = 0.f;

    const int n_stages = K / 16;

    auto issue = [&](int s, int buf) {
        const int k0 = s * 16;
        cp_async16(sA[buf] + (a_row * AST2 + a_c) * 2,
                   &A16[(size_t)(brow + a_row) * K + k0 + a_c]);
        cp_async16(sB[buf] + (b_row * BST2 + b_c) * 2,
                   &B16[(size_t)(k0 + b_row) * N + bcol + b_c]);
        cp_commit();
    };

    issue(0, 0);

    for (int s = 0; s < n_stages; s++) {
        const int buf = s & 1;
        if (s + 1 < n_stages) {
            issue(s + 1, buf ^ 1);
            asm volatile("cp.async.wait_group 1;");
        } else {
            asm volatile("cp.async.wait_group 0;");
        }
        __syncthreads();

        uint32_t bf[2][4];
        #pragma unroll
        for (int ng = 0; ng < 2; ng++) {
            uint32_t boff = (uint32_t)(
                (lane & 15) * BST2 + wn + ng * 16 + ((lane & 16) ? 8 : 0)) * 2u;
            ldmatrix_x4_trans(bf[ng][0], bf[ng][1], bf[ng][2], bf[ng][3],
                              sB[buf] + boff);
        }
        #pragma unroll
        for (int mt = 0; mt < 4; mt++) {
            uint32_t af[4];
            uint32_t aoff = (uint32_t)(
                (wm + mt * 16 + (lane & 15)) * AST2 + ((lane & 16) ? 8 : 0)) * 2u;
            ldmatrix_x4(af[0], af[1], af[2], af[3], sA[buf] + aoff);
            #pragma unroll
            for (int ng = 0; ng < 2; ng++) {
                #pragma unroll
                for (int hh = 0; hh < 2; hh++) {
                    mma_f16(acc[mt][ng * 2 + hh], af,
                            bf[ng][2 * hh], bf[ng][2 * hh + 1]);
                }
            }
        }
        __syncthreads();
    }

    if (mode == 0) {
        #pragma unroll
        for (int mt = 0; mt < 4; mt++) {
            #pragma unroll
            for (int nt = 0; nt < 4; nt++) {
                int row0 = brow + wm + mt * 16 + g;
                int col  = bcol + wn + nt * 8 + 2 * tg;
                float b0 = bias[col], b1 = bias[col + 1];
                float2 v0 = make_float2(acc[mt][nt][0] + b0, acc[mt][nt][1] + b1);
                float2 v1 = make_float2(acc[mt][nt][2] + b0, acc[mt][nt][3] + b1);
                *reinterpret_cast<float2*>(&Cmat[(size_t)row0 * N + col])       = v0;
                *reinterpret_cast<float2*>(&Cmat[(size_t)(row0 + 8) * N + col]) = v1;
            }
        }
    } else {
        const int seg = bcol / DMODEL;   // 0=Q, 1=K, 2=V (uniform per block)
        __half* dst = (seg == 0) ? q_out : (seg == 1) ? k_out : v_out;
        #pragma unroll
        for (int mt = 0; mt < 4; mt++) {
            #pragma unroll
            for (int nt = 0; nt < 4; nt++) {
                int row0  = brow + wm + mt * 16 + g;
                int colg  = bcol + wn + nt * 8 + 2 * tg;
                int colin = colg - seg * DMODEL;
                float b0 = bias[colg], b1 = bias[colg + 1];
                float fa0 = acc[mt][nt][0] + b0, fa1 = acc[mt][nt][1] + b1;
                float fb0 = acc[mt][nt][2] + b0, fb1 = acc[mt][nt][3] + b1;
                size_t d0 = (size_t)row0 * DMODEL + colin;
                size_t d1 = (size_t)(row0 + 8) * DMODEL + colin;
                *reinterpret_cast<uint32_t*>(&dst[d0]) =
                    h2_as_u32(__floats2half2_rn(fa0, fa1));
                *reinterpret_cast<uint32_t*>(&dst[d1]) =
                    h2_as_u32(__floats2half2_rn(fb0, fb1));
            }
        }
    }
}

// ---------------------------------------------------------------------------
// Tensor-core flash attention (causal), fp16 S + fp16 PV.
// 128-key KV LOAD tiles, processed as two 64-key sub-tiles sharing one
// load+sync pair: halves barrier count and load phases per key; fully-masked
// sub-tiles are skipped exactly. Register pressure identical to R13.
// ---------------------------------------------------------------------------
#define KS 72        // halves per K smem row: 36 words % 32 == 4 -> clean
#define VSTRIDE 72   // halves per V row
#define SUBOFF (64 * KS)   // halves offset of second sub-tile

__global__ __launch_bounds__(128)
void flash_attn_tc_kernel(const __half* __restrict__ gq,
                          const __half* __restrict__ gk,
                          const __half* __restrict__ gv,
                          __half* __restrict__ outa)
{
    __shared__ __half Kh[128 * KS];
    __shared__ __half Vs[128][VSTRIDE];

    const int qt   = (int)gridDim.x - 1 - (int)blockIdx.x;  // heavy tiles first
    const int h    = blockIdx.y;
    const int b    = blockIdx.z;
    const int tid  = threadIdx.x;
    const int warp = tid >> 5;
    const int lane = tid & 31;
    const int g    = lane >> 2;
    const int tg   = lane & 3;

    const uint32_t sKh = (uint32_t)__cvta_generic_to_shared(Kh);

    // Fold softmax scale and log2(e) into Q (softmax scale-invariant).
    const float qscale = 0.125f * 1.4426950408889634f;

    // --- Q fragments, fp16, m16n8k16 A layout; scale folded in ---
    uint32_t qf[4][4];
    {
        const __half* qbase =
            gq + (size_t)(b * SEQ + qt * 64 + warp * 16) * DMODEL + h * DHEAD;
        #pragma unroll
        for (int ks = 0; ks < 4; ks++) {
            #pragma unroll
            for (int j = 0; j < 4; j++) {
                int row = g + (j & 1) * 8;
                int col = ks * 16 + 2 * tg + (j & 2) * 4;
                uint32_t raw = *reinterpret_cast<const uint32_t*>(
                    &qbase[(size_t)row * DMODEL + col]);
                float2 f = __half22float2(u32_as_h2(raw));
                qf[ks][j] = h2_as_u32(
                    __floats2half2_rn(f.x * qscale, f.y * qscale));
            }
        }
    }

    float oacc[8][4];
    #pragma unroll
    for (int dt = 0; dt < 8; dt++)
        #pragma unroll
        for (int j = 0; j < 4; j++) oacc[dt][j] = 0.f;

    float m0 = -1e30f, m1 = -1e30f, l0 = 0.f, l1 = 0.f;

    const int n_kv2 = (qt >> 1) + 1;   // 128-key load tiles

    for (int kt2 = 0; kt2 < n_kv2; kt2++) {
        __syncthreads();
        // Cooperative copy of 128-key K and V tiles (uint4, 16 LDG/thread)
        #pragma unroll
        for (int it = 0; it < 8; it++) {
            int idx = it * 128 + tid;       // 0..1023
            int row = idx >> 3;             // key 0..127
            int c8  = idx & 7;              // 8-half group
            const size_t gidx =
                (size_t)(b * SEQ + kt2 * 128 + row) * DMODEL + h * DHEAD + c8 * 8;
            *reinterpret_cast<uint4*>(&Kh[row * KS + c8 * 8]) =
                *reinterpret_cast<const uint4*>(&gk[gidx]);
            *reinterpret_cast<uint4*>(&Vs[row][c8 * 8]) =
                *reinterpret_cast<const uint4*>(&gv[gidx]);
        }
        __syncthreads();

        #pragma unroll
        for (int half = 0; half < 2; half++) {
            const int kts = kt2 * 2 + half;   // 64-key sub-tile index
            if (kts > qt) break;              // fully masked -> skip exactly

            const uint32_t kbase = sKh + (uint32_t)(half * SUBOFF) * 2u;

            // --- S = Q·K^T (fp16 mma) ---
            float sacc[8][4];
            #pragma unroll
            for (int nt = 0; nt < 8; nt++)
                #pragma unroll
                for (int j = 0; j < 4; j++) sacc[nt][j] = 0.f;

            #pragma unroll
            for (int ks = 0; ks < 4; ks++) {
                #pragma unroll
                for (int ng = 0; ng < 4; ng++) {
                    uint32_t boff = (uint32_t)(
                        (ng * 16 + (lane & 15)) * KS +
                        ks * 16 + ((lane & 16) ? 8 : 0)) * 2u;
                    uint32_t b0, b1, b2, b3;
                    ldmatrix_x4(b0, b1, b2, b3, kbase + boff);
                    mma_f16(sacc[ng * 2],     qf[ks], b0, b2);
                    mma_f16(sacc[ng * 2 + 1], qf[ks], b1, b3);
                }
            }

            // --- causal mask on diagonal sub-tile ---
            if (kts == qt) {
                #pragma unroll
                for (int nt = 0; nt < 8; nt++) {
                    #pragma unroll
                    for (int j = 0; j < 4; j++) {
                        int row = warp * 16 + g + (j >> 1) * 8;
                        int col = nt * 8 + 2 * tg + (j & 1);
                        if (col > row) sacc[nt][j] = -1e30f;
                    }
                }
            }

            // --- online softmax (base-2) ---
            float mx0 = -1e30f, mx1 = -1e30f;
            #pragma unroll
            for (int nt = 0; nt < 8; nt++) {
                mx0 = fmaxf(mx0, fmaxf(sacc[nt][0], sacc[nt][1]));
                mx1 = fmaxf(mx1, fmaxf(sacc[nt][2], sacc[nt][3]));
            }
            mx0 = fmaxf(mx0, __shfl_xor_sync(0xffffffffu, mx0, 1));
            mx0 = fmaxf(mx0, __shfl_xor_sync(0xffffffffu, mx0, 2));
            mx1 = fmaxf(mx1, __shfl_xor_sync(0xffffffffu, mx1, 1));
            mx1 = fmaxf(mx1, __shfl_xor_sync(0xffffffffu, mx1, 2));

            float mn0 = fmaxf(m0, mx0);
            float mn1 = fmaxf(m1, mx1);
            float al0 = fast_exp2(m0 - mn0);
            float al1 = fast_exp2(m1 - mn1);

            float rs0 = 0.f, rs1 = 0.f;
            #pragma unroll
            for (int nt = 0; nt < 8; nt++) {
                float p0 = fast_exp2(sacc[nt][0] - mn0);
                float p1 = fast_exp2(sacc[nt][1] - mn0);
                float p2 = fast_exp2(sacc[nt][2] - mn1);
                float p3 = fast_exp2(sacc[nt][3] - mn1);
                sacc[nt][0] = p0; sacc[nt][1] = p1;
                sacc[nt][2] = p2; sacc[nt][3] = p3;
                rs0 += p0 + p1;
                rs1 += p2 + p3;
            }
            rs0 += __shfl_xor_sync(0xffffffffu, rs0, 1);
            rs0 += __shfl_xor_sync(0xffffffffu, rs0, 2);
            rs1 += __shfl_xor_sync(0xffffffffu, rs1, 1);
            rs1 += __shfl_xor_sync(0xffffffffu, rs1, 2);

            l0 = l0 * al0 + rs0;
            l1 = l1 * al1 + rs1;
            m0 = mn0;
            m1 = mn1;

            #pragma unroll
            for (int dt = 0; dt < 8; dt++) {
                oacc[dt][0] *= al0; oacc[dt][1] *= al0;
                oacc[dt][2] *= al1; oacc[dt][3] *= al1;
            }

            // --- O += P * V  (fp16 mma) ---
            #pragma unroll
            for (int ks = 0; ks < 4; ks++) {
                uint32_t pa[4];
                pa[0] = h2_as_u32(__floats2half2_rn(sacc[2*ks][0],   sacc[2*ks][1]));
                pa[1] = h2_as_u32(__floats2half2_rn(sacc[2*ks][2],   sacc[2*ks][3]));
                pa[2] = h2_as_u32(__floats2half2_rn(sacc[2*ks+1][0], sacc[2*ks+1][1]));
                pa[3] = h2_as_u32(__floats2half2_rn(sacc[2*ks+1][2], sacc[2*ks+1][3]));
                #pragma unroll
                for (int dp = 0; dp < 4; dp++) {
                    int krow = half * 64 + ks * 16 + (lane & 15);
                    int col  = dp * 16 + ((lane & 16) ? 8 : 0);
                    uint32_t addr =
                        (uint32_t)__cvta_generic_to_shared(&Vs[krow][col]);
                    uint32_t b0, b1, b2, b3;
                    ldmatrix_x4_trans(b0, b1, b2, b3, addr);
                    mma_f16(oacc[2 * dp],     pa, b0, b1);
                    mma_f16(oacc[2 * dp + 1], pa, b2, b3);
                }
            }
        }
    }

    // --- normalize + write fp16 ---
    const float inv0 = 1.f / l0;
    const float inv1 = 1.f / l1;
    const size_t obase =
        (size_t)(b * SEQ + qt * 64 + warp * 16) * DMODEL + h * DHEAD;
    #pragma unroll
    for (int dt = 0; dt < 8; dt++) {
        int col = dt * 8 + 2 * tg;
        size_t i0 = obase + (size_t)g * DMODEL + col;
        size_t i1 = obase + (size_t)(g + 8) * DMODEL + col;
        *reinterpret_cast<uint32_t*>(&outa[i0]) = h2_as_u32(
            __floats2half2_rn(oacc[dt][0] * inv0, oacc[dt][1] * inv0));
        *reinterpret_cast<uint32_t*>(&outa[i1]) = h2_as_u32(
            __floats2half2_rn(oacc[dt][2] * inv1, oacc[dt][3] * inv1));
    }
}

// ---------------------------------------------------------------------------
// Launch
// ---------------------------------------------------------------------------
extern "C" void kernel_launch(void* const* d_in, const int* in_sizes, int n_in,
                              void* d_out, int out_size)
{
    const float* x      = (const float*)d_in[0];
    const float* W_qkv  = (const float*)d_in[1];
    const float* b_qkv  = (const float*)d_in[2];
    const float* W_proj = (const float*)d_in[3];
    const float* b_proj = (const float*)d_in[4];
    float* out = (float*)d_out;

    void *p_x16, *p_wq16, *p_wp16, *p_q16, *p_k16, *p_v16, *p_at16;
    cudaGetSymbolAddress(&p_x16, g_x16);
    cudaGetSymbolAddress(&p_wq16, g_wq16);
    cudaGetSymbolAddress(&p_wp16, g_wp16);
    cudaGetSymbolAddress(&p_q16, g_q16);
    cudaGetSymbolAddress(&p_k16, g_k16);
    cudaGetSymbolAddress(&p_v16, g_v16);
    cudaGetSymbolAddress(&p_at16, g_at16);

    __half* x16  = (__half*)p_x16;
    __half* wq16 = (__half*)p_wq16;
    __half* wp16 = (__half*)p_wp16;
    __half* q16  = (__half*)p_q16;
    __half* k16  = (__half*)p_k16;
    __half* v16  = (__half*)p_v16;
    __half* at16 = (__half*)p_at16;

    // 0) fp32 -> fp16 input converts (streaming)
    cvt16_kernel<<<BT * DMODEL / 4 / 256, 256>>>(x, x16);
    cvt16_kernel<<<DMODEL * C3 / 4 / 256, 256>>>(W_qkv, wq16);
    cvt16_kernel<<<DMODEL * DMODEL / 4 / 256, 256>>>(W_proj, wp16);

    // 1) QKV projection (fp16 mma); fused epilogue writes Q/K/V fp16
    {
        dim3 grid(C3 / 128, BT / 128);
        gemm_f16_async_kernel<<<grid, 256>>>(x16, wq16, b_qkv,
                                             nullptr, BT, C3, DMODEL,
                                             1, q16, k16, v16);
    }

    // 2) Causal flash attention (128-key load tiles); writes att fp16
    {
        dim3 grid(SEQ / 64, NHEADS, BATCH);
        flash_attn_tc_kernel<<<grid, 128>>>(q16, k16, v16, at16);
    }

    // 3) Output projection (fp16 mma, fp32 epilogue + bias)
    {
        dim3 grid(DMODEL / 128, BT / 128);
        gemm_f16_async_kernel<<<grid, 256>>>(at16, wp16, b_proj,
                                             out, BT, DMODEL, DMODEL,
                                             0, nullptr, nullptr, nullptr);
    }
}